// round 12
// baseline (speedup 1.0000x reference)
#include <cuda_runtime.h>
#include <stdint.h>

// ---------------------------------------------------------------------------
// W4A8 per-group GEMM via legacy fp16 HMMA with magic-number int8->fp16.
// R11 was L2-bound (61.7%): bf16 A-fragments doubled x's bytes and all 448
// CTAs re-read them through L2 (smem 67.5KB x3 leaves ~26KB L1). Round 12:
//  - A-frags stored as u8 (x+128) -> half the A L2 traffic; per-group slice
//    8KB fits residual L1 for cross-CTA reuse
//  - in-register u8->fp16: prmt (byte splice into 0x64xx = 1024+u) +
//    sub.f16x2 by 1152 -> exact fp16 integers (2 ops/word)
//  - B dequant: u=q*s2+(z+128) in [23,233]; (u0|u1<<16)|0x64006400, sub 1152
//  - mma.m16n8k16.f32.f16.f16.f32 (same legacy HMMA pipe, ~12us busy)
// Rest = R11: 2 groups per __syncthreads (4 B buffers), cp.async raw qweight,
// warps split K (4wm x 2kh), smem k-half reduction. Exact: all operands are
// <=8-bit integers in fp16; fp32 accumulation (validated rel_err 4.4e-8).
// ---------------------------------------------------------------------------

#define M_DIM 64
#define K_DIM 4096
#define N_DIM 14336
#define G_DIM 32
#define NT    32             // output channels per CTA -> 448 CTAs
#define BROW  272            // fp16 B-tile row bytes (256 data + 16 pad)
#define THREADS 256
#define TILE_B (NT * BROW)           // 8704
#define RAW_BYTES 16384              // one group: 32 rows x 128 ints x 4B
#define OFF_RAW(b)  ((b) * RAW_BYTES)
#define OFF_B(i)    (2 * RAW_BYTES + (i) * TILE_B)
#define SMEM_TOTAL  (2 * RAW_BYTES + 4 * TILE_B)   // 67584

#define C_MAGIC 0x64006400u   // fp16x2 {1024.0, 1024.0} bit pattern
#define C_BIAS  0x64806480u   // fp16x2 {1152.0, 1152.0}
#define C_SEL   0x64646464u   // byte source for prmt exponent splice

#define CP_ASYNC16(dst, src) \
    asm volatile("cp.async.cg.shared.global [%0], [%1], 16;" :: "r"(dst), "l"(src))
#define CP_COMMIT()  asm volatile("cp.async.commit_group;")
#define CP_WAIT(N)   asm volatile("cp.async.wait_group %0;" :: "n"(N))

__device__ __forceinline__ unsigned smem_u32(const void* p) {
    unsigned a;
    asm("{ .reg .u64 t; cvta.to.shared.u64 t, %1; cvt.u32.u64 %0, t; }" : "=r"(a) : "l"(p));
    return a;
}
__device__ __forceinline__ unsigned prmt(unsigned a, unsigned b, unsigned s) {
    unsigned r;
    asm("prmt.b32 %0, %1, %2, %3;" : "=r"(r) : "r"(a), "r"(b), "r"(s));
    return r;
}
__device__ __forceinline__ unsigned hsub2(unsigned a, unsigned b) {
    unsigned r;
    asm("sub.rn.f16x2 %0, %1, %2;" : "=r"(r) : "r"(a), "r"(b));
    return r;
}

// A fragments as u8 (x+128), mma register order:
// uint2 index = g*1024 + wm*256 + kh*128 + ks*32 + lane   (256 KB total)
// word .x = [u(r0,k0), u(r0,k1), u(r1,k0), u(r1,k1)], .y same for k+8
__device__ __align__(16) uint2 g_x_frag[G_DIM * 4 * 2 * 4 * 32];

// ---- pass 0: pack x int32 -> u8 A-fragments -----------------------------------
__global__ void pack_x_frag_kernel(const int* __restrict__ x) {
    const int t = blockIdx.x * blockDim.x + threadIdx.x;
    if (t >= G_DIM * 1024) return;
    const int lane = t & 31;
    const int ks   = (t >> 5) & 3;
    const int kh   = (t >> 7) & 1;
    const int wm   = (t >> 8) & 3;
    const int g    = t >> 10;
    const int g4 = lane >> 2, tg = lane & 3;
    const int r0 = wm * 16 + g4, r1 = r0 + 8;
    const int kb = g * 128 + kh * 64 + ks * 16 + tg * 2;
    const int* x0 = x + r0 * K_DIM + kb;
    const int* x1 = x + r1 * K_DIM + kb;
    uint2 v;
    v.x = __byte_perm(__byte_perm((unsigned)(x0[0] + 128), (unsigned)(x0[1] + 128), 0x0040),
                      __byte_perm((unsigned)(x1[0] + 128), (unsigned)(x1[1] + 128), 0x0040),
                      0x5410);
    v.y = __byte_perm(__byte_perm((unsigned)(x0[8] + 128), (unsigned)(x0[9] + 128), 0x0040),
                      __byte_perm((unsigned)(x1[8] + 128), (unsigned)(x1[9] + 128), 0x0040),
                      0x5410);
    g_x_frag[t] = v;
}

// one group's MMA: 4 k16-steps x n32; A fragments from preloaded u8 words
__device__ __forceinline__ void mma_group(float acc[4][4], const uint2 av[4], unsigned bA) {
#pragma unroll
    for (int ks = 0; ks < 4; ks++) {
        const unsigned a0 = hsub2(prmt(av[ks].x, C_SEL, 0x4140), C_BIAS);
        const unsigned a1 = hsub2(prmt(av[ks].x, C_SEL, 0x4342), C_BIAS);
        const unsigned a2 = hsub2(prmt(av[ks].y, C_SEL, 0x4140), C_BIAS);
        const unsigned a3 = hsub2(prmt(av[ks].y, C_SEL, 0x4342), C_BIAS);
        unsigned b0, b1, b2, b3, b4, b5, b6, b7;
        asm volatile(
            "ldmatrix.sync.aligned.m8n8.x4.shared.b16 {%0,%1,%2,%3}, [%4];"
            : "=r"(b0), "=r"(b1), "=r"(b2), "=r"(b3)
            : "r"(bA + ks * 32));
        asm volatile(
            "ldmatrix.sync.aligned.m8n8.x4.shared.b16 {%0,%1,%2,%3}, [%4];"
            : "=r"(b4), "=r"(b5), "=r"(b6), "=r"(b7)
            : "r"(bA + 16 * BROW + ks * 32));
        asm volatile(
            "mma.sync.aligned.m16n8k16.row.col.f32.f16.f16.f32 "
            "{%0,%1,%2,%3}, {%4,%5,%6,%7}, {%8,%9}, {%0,%1,%2,%3};\n"
            : "+f"(acc[0][0]), "+f"(acc[0][1]), "+f"(acc[0][2]), "+f"(acc[0][3])
            : "r"(a0), "r"(a1), "r"(a2), "r"(a3), "r"(b0), "r"(b1));
        asm volatile(
            "mma.sync.aligned.m16n8k16.row.col.f32.f16.f16.f32 "
            "{%0,%1,%2,%3}, {%4,%5,%6,%7}, {%8,%9}, {%0,%1,%2,%3};\n"
            : "+f"(acc[1][0]), "+f"(acc[1][1]), "+f"(acc[1][2]), "+f"(acc[1][3])
            : "r"(a0), "r"(a1), "r"(a2), "r"(a3), "r"(b2), "r"(b3));
        asm volatile(
            "mma.sync.aligned.m16n8k16.row.col.f32.f16.f16.f32 "
            "{%0,%1,%2,%3}, {%4,%5,%6,%7}, {%8,%9}, {%0,%1,%2,%3};\n"
            : "+f"(acc[2][0]), "+f"(acc[2][1]), "+f"(acc[2][2]), "+f"(acc[2][3])
            : "r"(a0), "r"(a1), "r"(a2), "r"(a3), "r"(b4), "r"(b5));
        asm volatile(
            "mma.sync.aligned.m16n8k16.row.col.f32.f16.f16.f32 "
            "{%0,%1,%2,%3}, {%4,%5,%6,%7}, {%8,%9}, {%0,%1,%2,%3};\n"
            : "+f"(acc[3][0]), "+f"(acc[3][1]), "+f"(acc[3][2]), "+f"(acc[3][3])
            : "r"(a0), "r"(a1), "r"(a2), "r"(a3), "r"(b6), "r"(b7));
    }
}

// ---- main GEMM ---------------------------------------------------------------
__global__ __launch_bounds__(THREADS, 3)
void w4a8_gemm_kernel(const int*   __restrict__ qw,    // [N,K] int32 (0..15)
                      const int*   __restrict__ s2s,   // [G,N]
                      const int*   __restrict__ s2z,   // [G,N]
                      const float* __restrict__ isc,   // [M]
                      const float* __restrict__ s1,    // [N]
                      const float* __restrict__ bias,  // [N]
                      float*       __restrict__ out)   // [M,N]
{
    extern __shared__ __align__(16) unsigned char smem[];
    const unsigned sbase = smem_u32(smem);

    const int tid = threadIdx.x;
    const int n0  = blockIdx.x * NT;

    // qweight producer mapping: thread -> (row 0..31, 64B slice 0..7 of a group)
    const int brow = tid >> 3;
    const int bseg = tid & 7;
    const char* gsrc = reinterpret_cast<const char*>(qw + (size_t)(n0 + brow) * K_DIM)
                     + bseg * 64;
    const unsigned roffc = (unsigned)brow * 512u + (unsigned)bseg * 16u;
    const unsigned bSto  = (unsigned)brow * BROW + (unsigned)bseg * 32u;

    // warp org: 4 wm (m16 rows) x 2 kh (k-halves of each group)
    const int warp = tid >> 5, lane = tid & 31;
    const int wm = warp >> 1;
    const int kh = warp & 1;
    const int g4 = lane >> 2, tg = lane & 3;

    // A-fragment gmem pointer (uint2 units)
    const uint2* aptr = g_x_frag + wm * 256 + kh * 128 + lane;

    // B ldmatrix base (buffer 0)
    const unsigned bAddr0 = sbase + OFF_B(0)
        + (unsigned)(((lane >> 4) & 1) * 8 + (lane & 7)) * BROW
        + (unsigned)kh * 128u + (unsigned)((lane >> 3) & 1) * 16u;

    float acc[4][4];
#pragma unroll
    for (int i = 0; i < 4; i++)
#pragma unroll
        for (int j = 0; j < 4; j++) acc[i][j] = 0.0f;

    // ---- prologue: stream raw groups 0 (raw0) and 1 (raw1) ----
#pragma unroll
    for (int s = 0; s < 2; s++) {
        const unsigned dst = sbase + OFF_RAW(s) + roffc;
        const char* src = gsrc + (size_t)s * 512;
#pragma unroll
        for (int j = 0; j < 4; j++) CP_ASYNC16(dst + j * 128u, src + j * 16);
        CP_COMMIT();
    }
    int s2a = s2s[n0 + brow],         za = s2z[n0 + brow] + 128;
    int s2b = s2s[N_DIM + n0 + brow], zb = s2z[N_DIM + n0 + brow] + 128;

    for (int p = 0; p < G_DIM / 2; ++p) {
        const int a  = 2 * p;
        const int bb = 2 * (p & 1);     // B buffer pair {bb, bb+1}

        // A fragments for group a (u8, L1/L2-hot)
        uint2 ava[4];
        {
            const uint2* ap = aptr + a * 1024;
#pragma unroll
            for (int k = 0; k < 4; k++) ava[k] = ap[k * 32];
        }

        // ---- consume raw0 (group a): dequant fp16 -> sB[bb], refill a+2 ----
        CP_WAIT(1);
#pragma unroll
        for (int h = 0; h < 2; h++) {   // h=0: raw0/group a ; h=1: raw1/group a+1
            if (h == 1) { if (p == G_DIM / 2 - 1) { CP_WAIT(0); } else { CP_WAIT(1); } }
            const int s2 = h ? s2b : s2a;
            const int zz = h ? zb  : za;
            unsigned pk[8];
#pragma unroll
            for (int j = 0; j < 4; j++) {
                int4 q = *reinterpret_cast<const int4*>(
                    smem + OFF_RAW(h) + roffc + j * 128u);
                const unsigned u0 = (unsigned)(q.x * s2 + zz);
                const unsigned u1 = (unsigned)(q.y * s2 + zz);
                const unsigned u2 = (unsigned)(q.z * s2 + zz);
                const unsigned u3 = (unsigned)(q.w * s2 + zz);
                pk[2 * j]     = hsub2((u0 | (u1 << 16)) | C_MAGIC, C_BIAS);
                pk[2 * j + 1] = hsub2((u2 | (u3 << 16)) | C_MAGIC, C_BIAS);
            }
            unsigned char* dst = smem + OFF_B(bb + h) + bSto;
            *reinterpret_cast<uint4*>(dst)      = make_uint4(pk[0], pk[1], pk[2], pk[3]);
            *reinterpret_cast<uint4*>(dst + 16) = make_uint4(pk[4], pk[5], pk[6], pk[7]);
            // refill this raw buffer with group a+2+h
            if (a + 2 + h < G_DIM) {
                const unsigned rdst = sbase + OFF_RAW(h) + roffc;
                const char* src = gsrc + (size_t)(a + 2 + h) * 512;
#pragma unroll
                for (int j = 0; j < 4; j++) CP_ASYNC16(rdst + j * 128u, src + j * 16);
                CP_COMMIT();
            }
        }

        // ---- prefetch next pair's scales ----
        if (p + 1 < G_DIM / 2) {
            s2a = s2s[(a + 2) * N_DIM + n0 + brow];
            za  = s2z[(a + 2) * N_DIM + n0 + brow] + 128;
            s2b = s2s[(a + 3) * N_DIM + n0 + brow];
            zb  = s2z[(a + 3) * N_DIM + n0 + brow] + 128;
        }

        __syncthreads();   // ONE barrier per 2 groups

        // ---- MMA group a, then group a+1 ----
        {
            uint2 avb[4];
            const uint2* ap = aptr + (a + 1) * 1024;
#pragma unroll
            for (int k = 0; k < 4; k++) avb[k] = ap[k * 32];
            mma_group(acc, ava, bAddr0 + (unsigned)bb * TILE_B);
            mma_group(acc, avb, bAddr0 + (unsigned)(bb + 1) * TILE_B);
        }
    }

    // ---- k-half reduction via smem (raw buffers are dead now) ----
    __syncthreads();
    float* sRed = reinterpret_cast<float*>(smem);   // [64][32] f32 = 8KB
    const int rbase0 = (wm * 16 + g4) * 32 + tg * 2;
    if (kh == 1) {
#pragma unroll
        for (int ns = 0; ns < 4; ns++) {
            sRed[rbase0 + ns * 8]           = acc[ns][0];
            sRed[rbase0 + ns * 8 + 1]       = acc[ns][1];
            sRed[rbase0 + 256 + ns * 8]     = acc[ns][2];   // row +8
            sRed[rbase0 + 256 + ns * 8 + 1] = acc[ns][3];
        }
    }
    __syncthreads();
    if (kh == 0) {
        const int m0 = wm * 16 + g4;
        const float isc0 = isc[m0];
        const float isc1 = isc[m0 + 8];
#pragma unroll
        for (int ns = 0; ns < 4; ns++) {
            const int n = n0 + ns * 8 + tg * 2;
            const float s1a = s1[n],   s1b = s1[n + 1];
            const float ba2 = bias[n], bb2 = bias[n + 1];
            const float v0 = acc[ns][0] + sRed[rbase0 + ns * 8];
            const float v1 = acc[ns][1] + sRed[rbase0 + ns * 8 + 1];
            const float v2 = acc[ns][2] + sRed[rbase0 + 256 + ns * 8];
            const float v3 = acc[ns][3] + sRed[rbase0 + 256 + ns * 8 + 1];
            out[ m0      * N_DIM + n    ] = v0 * isc0 * s1a + ba2;
            out[ m0      * N_DIM + n + 1] = v1 * isc0 * s1b + bb2;
            out[(m0 + 8) * N_DIM + n    ] = v2 * isc1 * s1a + ba2;
            out[(m0 + 8) * N_DIM + n + 1] = v3 * isc1 * s1b + bb2;
        }
    }
}

// ---------------------------------------------------------------------------
extern "C" void kernel_launch(void* const* d_in, const int* in_sizes, int n_in,
                              void* d_out, int out_size) {
    const int*   x    = (const int*)  d_in[0];  // [M,K] int32 (int8 values)
    const float* isc  = (const float*)d_in[1];  // [M]
    // d_in[2] = input_sum (unused)
    const int*   qw   = (const int*)  d_in[3];  // [N,K] int32 (uint4 values)
    const int*   s2s  = (const int*)  d_in[4];  // [G,N]
    const int*   s2z  = (const int*)  d_in[5];  // [G,N]
    const float* s1   = (const float*)d_in[6];  // [N]
    const float* bias = (const float*)d_in[7];  // [N]
    float* out = (float*)d_out;

    cudaFuncSetAttribute(w4a8_gemm_kernel,
                         cudaFuncAttributeMaxDynamicSharedMemorySize, SMEM_TOTAL);

    pack_x_frag_kernel<<<G_DIM * 1024 / 256, 256>>>(x);
    w4a8_gemm_kernel<<<N_DIM / NT, THREADS, SMEM_TOTAL>>>(qw, s2s, s2z, isc, s1, bias, out);
}